// round 14
// baseline (speedup 1.0000x reference)
#include <cuda_runtime.h>
#include <cstdint>

#define D_MODEL 2048
#define BATCH   16384
#define MT 256
#define NT 64
#define A_STAGE 32768
#define STAGE_BYTES 45056        // A 32KB + B 12KB
#define SMEM_TOTAL (5*STAGE_BYTES + 512)   // 225792 <= 232448, 1 CTA/SM

// scratch: x in A-fragment order, weights in B-fragment order, decay partials
__device__ float g_xA[33554432];   // [rt 0..1023][t 0..255][128 w]
__device__ float g_WB[6291456];    // [cb 0..31][bt 0..11][t 0..255][64 w]
__device__ float g_dpart[65536];   // [tb 0..3][row 0..16383] partial decay dots

__device__ __forceinline__ float tf32r(float x) {
    float y; asm("cvt.rna.tf32.f32 %0, %1;" : "=f"(y) : "f"(x)); return y;
}
__device__ __forceinline__ uint32_t smem_u32(const void* p) {
    uint32_t a;
    asm("{ .reg .u64 t; cvta.to.shared.u64 t, %1; cvt.u32.u64 %0, t; }" : "=r"(a) : "l"(p));
    return a;
}
__device__ __forceinline__ void cp16(uint32_t dst, const void* src) {
    asm volatile("cp.async.cg.shared.global [%0], [%1], 16;" :: "r"(dst), "l"(src));
}
__device__ __forceinline__ void lds128(uint32_t* r, uint32_t a) {
    asm volatile("ld.shared.v4.b32 {%0,%1,%2,%3}, [%4];"
                 : "=r"(r[0]), "=r"(r[1]), "=r"(r[2]), "=r"(r[3]) : "r"(a));
}
__device__ __forceinline__ void lds64(uint32_t* r, uint32_t a) {
    asm volatile("ld.shared.v2.b32 {%0,%1}, [%2];" : "=r"(r[0]), "=r"(r[1]) : "r"(a));
}
__device__ __forceinline__ void mma_tf32(float* c, const uint32_t* a, const uint32_t* b) {
    asm volatile(
        "mma.sync.aligned.m16n8k8.row.col.f32.tf32.tf32.f32 "
        "{%0,%1,%2,%3}, {%4,%5,%6,%7}, {%8,%9}, {%0,%1,%2,%3};\n"
        : "+f"(c[0]), "+f"(c[1]), "+f"(c[2]), "+f"(c[3])
        : "r"(a[0]), "r"(a[1]), "r"(a[2]), "r"(a[3]), "r"(b[0]), "r"(b[1]));
}

// ---- preround x + conflict-free fused decay partial (42us, R13 verbatim) ----
__global__ __launch_bounds__(256) void preround_x(const float* __restrict__ x,
                                                  const float* __restrict__ Wd) {
    __shared__ float sm[16 * 516];
    const int tid = threadIdx.x;
    const int rt = blockIdx.x >> 2, tb = blockIdx.x & 3;
    const float* src = x + (size_t)rt * 16 * D_MODEL + tb * 512;
    #pragma unroll
    for (int i = 0; i < 8; i++) {
        int f4 = tid + i * 256;
        int row = f4 >> 7, c4 = f4 & 127;
        float4 v = *(const float4*)(src + (size_t)row * D_MODEL + c4 * 4);
        v.x = tf32r(v.x); v.y = tf32r(v.y); v.z = tf32r(v.z); v.w = tf32r(v.w);
        *(float4*)&sm[row * 516 + c4 * 4] = v;
    }
    __syncthreads();
    char* dst = (char*)g_xA + (size_t)rt * 131072 + (size_t)tb * 64 * 512;
    #pragma unroll
    for (int i = 0; i < 8; i++) {
        int f4 = tid + i * 256;
        int tl = f4 >> 5, lane = f4 & 31;
        int g = lane >> 2, tg = lane & 3;
        float4 v;
        v.x = sm[ g      * 516 + tl * 8 + tg    ];
        v.y = sm[(g + 8) * 516 + tl * 8 + tg    ];
        v.z = sm[ g      * 516 + tl * 8 + tg + 4];
        v.w = sm[(g + 8) * 516 + tl * 8 + tg + 4];
        *(float4*)(dst + (size_t)tl * 512 + lane * 16) = v;
    }
    {
        const int r = tid >> 4, sub = tid & 15;
        const float4* wd4 = (const float4*)Wd + tb * 128;
        float s = 0.f;
        #pragma unroll
        for (int j = 0; j < 8; j++) {
            int jj = (j + sub) & 7;
            float4 a = *(const float4*)&sm[r * 516 + sub * 32 + jj * 4];
            float4 w = wd4[sub * 8 + jj];
            s += a.x * w.x + a.y * w.y + a.z * w.z + a.w * w.w;
        }
        #pragma unroll
        for (int o = 1; o < 16; o <<= 1) s += __shfl_xor_sync(0xFFFFFFFFu, s, o);
        if (sub == 0) g_dpart[tb * 16384 + rt * 16 + r] = s;
    }
}

// ---- preround W (staged, R13 verbatim) ----
__global__ __launch_bounds__(256) void preround_w(const float* __restrict__ Wi,
                                                  const float* __restrict__ Wa) {
    __shared__ float sm[8 * 516];
    const int tid = threadIdx.x;
    const int q  = blockIdx.x & 3;
    const int bt = (blockIdx.x >> 2) % 12;
    const int cb = blockIdx.x / 48;
    const float* src = (bt < 8)
        ? Wi + (size_t)(cb * 64 + bt * 8) * D_MODEL
        : Wa + (size_t)(cb * 32 + (bt - 8) * 8) * D_MODEL;
    src += q * 512;
    #pragma unroll
    for (int i = 0; i < 4; i++) {
        int f4 = tid + i * 256;
        int r = f4 >> 7, c4 = f4 & 127;
        float4 v = *(const float4*)(src + (size_t)r * D_MODEL + c4 * 4);
        v.x = tf32r(v.x); v.y = tf32r(v.y); v.z = tf32r(v.z); v.w = tf32r(v.w);
        *(float4*)&sm[r * 516 + c4 * 4] = v;
    }
    __syncthreads();
    float* dst = g_WB + (size_t)(cb * 12 + bt) * 16384 + (size_t)q * 64 * 64;
    #pragma unroll
    for (int i = 0; i < 4; i++) {
        int f4 = tid + i * 256;
        int tl = f4 >> 4, m = f4 & 15;
        int g = m >> 1, tg0 = (m & 1) * 2, tg1 = tg0 + 1;
        float4 v;
        v.x = sm[g * 516 + tl * 8 + tg0    ];
        v.y = sm[g * 516 + tl * 8 + tg0 + 4];
        v.z = sm[g * 516 + tl * 8 + tg1    ];
        v.w = sm[g * 516 + tl * 8 + tg1 + 4];
        *(float4*)(dst + tl * 64 + m * 4) = v;
    }
}

// ---- main: MT=256, 256 thr, 8 warps (4x2), 5 stages, wait_group 1 ----
__global__ void __launch_bounds__(256, 1) givens_main(
    const float* __restrict__ h_prev, const float* __restrict__ b_angle,
    const float* __restrict__ b_decay, const float* __restrict__ b_in,
    float* __restrict__ out)
{
    extern __shared__ __align__(1024) char smem[];
    const uint32_t sb = smem_u32(smem);
    const int tid = threadIdx.x, warp = tid >> 5, lane = tid & 31;
    const int g = lane >> 2, tg = lane & 3;
    const int wm = warp >> 1, wn = warp & 1;            // 4x2 warp grid
    const int by = blockIdx.y, cb = blockIdx.x;
    const int m0 = by * MT, n0 = cb * NT, a0 = n0 >> 1;

    // A: 16 lrt per CTA, 2048 granules; 8 per thread (R5-proven scheme)
    const char* xA = (const char*)g_xA + (size_t)by * 2097152;
    const char* WB = (const char*)g_WB + (size_t)cb * 786432;
    const char* asrc[8]; uint32_t adst[8];
    #pragma unroll
    for (int it = 0; it < 8; it++) {
        int f4 = it * 256 + tid;
        int lrt = f4 >> 7, inner = f4 & 127;
        asrc[it] = xA + (size_t)lrt * 131072 + inner * 16;
        adst[it] = (uint32_t)(f4 * 16);
    }
    // B: 12 bt, 768 granules; 3 per thread
    const char* bsrc[3]; uint32_t bdst[3];
    #pragma unroll
    for (int ib = 0; ib < 3; ib++) {
        int f4 = ib * 256 + tid;
        int bt = f4 >> 6, inner = f4 & 63;
        bsrc[ib] = WB + (size_t)bt * 65536 + inner * 16;
        bdst[ib] = (uint32_t)(A_STAGE + f4 * 16);
    }

    float ci[4][4][4] = {};   // mi, nb, frag
    float ca[4][2][4] = {};   // mi, na, frag

    #define ISSUE(CHUNK) do {                                                   \
        uint32_t sd = sb + ((CHUNK) % 5) * STAGE_BYTES;                          \
        _Pragma("unroll")                                                        \
        for (int it = 0; it < 8; it++)                                           \
            cp16(sd + adst[it], asrc[it] + (size_t)(CHUNK) * 2048);              \
        _Pragma("unroll")                                                        \
        for (int ib = 0; ib < 3; ib++)                                           \
            cp16(sd + bdst[ib], bsrc[ib] + (size_t)(CHUNK) * 1024);              \
        asm volatile("cp.async.commit_group;" ::: "memory");                     \
    } while (0)

    #define COMPUTE(CHUNK) do {                                                  \
        const uint32_t sa = sb + ((CHUNK) % 5) * STAGE_BYTES;                     \
        _Pragma("unroll")                                                         \
        for (int kt = 0; kt < 4; kt++) {                                          \
            uint32_t a[4][4];                                                     \
            _Pragma("unroll")                                                     \
            for (int mi = 0; mi < 4; mi++)                                        \
                lds128(a[mi], sa + (uint32_t)(((wm * 4 + mi) * 4 + kt) * 512) + lane * 16); \
            _Pragma("unroll")                                                     \
            for (int nb = 0; nb < 4; nb++) {                                      \
                uint32_t b[2];                                                    \
                lds64(b, sa + A_STAGE + (uint32_t)(((wn * 4 + nb) * 4 + kt) * 256) + lane * 8); \
                _Pragma("unroll")                                                 \
                for (int mi = 0; mi < 4; mi++) mma_tf32(ci[mi][nb], a[mi], b);    \
            }                                                                     \
            _Pragma("unroll")                                                     \
            for (int na = 0; na < 2; na++) {                                      \
                uint32_t b[2];                                                    \
                lds64(b, sa + A_STAGE + (uint32_t)(((8 + wn * 2 + na) * 4 + kt) * 256) + lane * 8); \
                _Pragma("unroll")                                                 \
                for (int mi = 0; mi < 4; mi++) mma_tf32(ca[mi][na], a[mi], b);    \
            }                                                                     \
        }                                                                         \
    } while (0)

    ISSUE(0); ISSUE(1); ISSUE(2);

    #pragma unroll 1
    for (int cc = 0; cc < 32; cc++) {
        const int c0 = cc * 2;
        asm volatile("cp.async.wait_group 1;" ::: "memory");   // c0, c0+1 landed
        __syncthreads();
        if (c0 + 3 < 64) ISSUE(c0 + 3);
        else             asm volatile("cp.async.commit_group;" ::: "memory");
        if (c0 + 4 < 64) ISSUE(c0 + 4);
        else             asm volatile("cp.async.commit_group;" ::: "memory");
        COMPUTE(c0);
        COMPUTE(c0 + 1);
    }
    __syncthreads();

    // ---- epilogue ----
    float* ang_sm = (float*)smem;                       // 256 x 33 (stage reuse)
    #pragma unroll
    for (int mi = 0; mi < 4; mi++)
    #pragma unroll
    for (int na = 0; na < 2; na++) {
        int rm  = wm * 64 + mi * 16 + g;
        int cbp = wn * 16 + na * 8 + 2 * tg;
        float bA0 = b_angle[a0 + cbp], bA1 = b_angle[a0 + cbp + 1];
        ang_sm[ rm      * 33 + cbp    ] = ca[mi][na][0] + bA0;
        ang_sm[ rm      * 33 + cbp + 1] = ca[mi][na][1] + bA1;
        ang_sm[(rm + 8) * 33 + cbp    ] = ca[mi][na][2] + bA0;
        ang_sm[(rm + 8) * 33 + cbp + 1] = ca[mi][na][3] + bA1;
    }
    const float bdec = b_decay[0];
    float drow[4][2];
    #pragma unroll
    for (int mi = 0; mi < 4; mi++)
    #pragma unroll
    for (int h = 0; h < 2; h++) {
        int r = m0 + wm * 64 + mi * 16 + g + h * 8;
        float s = g_dpart[r] + g_dpart[16384 + r] + g_dpart[32768 + r] + g_dpart[49152 + r];
        drow[mi][h] = 1.f / (1.f + __expf(-(s + bdec)));
    }
    __syncthreads();

    #pragma unroll
    for (int mi = 0; mi < 4; mi++)
    #pragma unroll
    for (int nb = 0; nb < 4; nb++) {
        int cloc = wn * 32 + nb * 8 + 2 * tg;
        float2 bi2 = *(const float2*)&b_in[n0 + cloc];
        #pragma unroll
        for (int h = 0; h < 2; h++) {
            int rloc = wm * 64 + mi * 16 + g + h * 8;
            size_t goff = (size_t)(m0 + rloc) * D_MODEL + n0 + cloc;
            float theta = ang_sm[rloc * 33 + (cloc >> 1)];
            float sn, cs;
            __sincosf(theta, &sn, &cs);
            float2 hp = *(const float2*)&h_prev[goff];
            float d = drow[mi][h];
            float2 o;
            o.x = d * (cs * hp.x - sn * hp.y) + ci[mi][nb][h * 2 + 0] + bi2.x;
            o.y = d * (sn * hp.x + cs * hp.y) + ci[mi][nb][h * 2 + 1] + bi2.y;
            *(float2*)&out[goff] = o;
        }
    }
    #undef ISSUE
    #undef COMPUTE
}

extern "C" void kernel_launch(void* const* d_in, const int* in_sizes, int n_in,
                              void* d_out, int out_size) {
    const float* x       = (const float*)d_in[0];
    const float* h_prev  = (const float*)d_in[1];
    const float* W_angle = (const float*)d_in[2];
    const float* b_angle = (const float*)d_in[3];
    const float* W_decay = (const float*)d_in[4];
    const float* b_decay = (const float*)d_in[5];
    const float* W_in    = (const float*)d_in[6];
    const float* b_in    = (const float*)d_in[7];

    preround_x<<<4096, 256>>>(x, W_decay);
    preround_w<<<1536, 256>>>(W_in, W_angle);

    cudaFuncSetAttribute(givens_main, cudaFuncAttributeMaxDynamicSharedMemorySize, SMEM_TOTAL);
    dim3 grid(D_MODEL / NT, BATCH / MT);
    givens_main<<<grid, 256, SMEM_TOTAL>>>(h_prev, b_angle, b_decay, b_in, (float*)d_out);
}

// round 15
// speedup vs baseline: 1.2279x; 1.2279x over previous
#include <cuda_runtime.h>
#include <cstdint>

#define D_MODEL 2048
#define BATCH   16384
#define MT 128
#define NT 64
#define A_STAGE 16384
#define STAGE_BYTES 28672        // A 16KB + B 12KB
#define SMEM_TOTAL (4*STAGE_BYTES + 512)   // 115200/CTA, 2 CTA/SM

// scratch: x in A-fragment order, weights in B-pair-fragment order, decay partials
__device__ float g_xA[33554432];   // [rt 0..1023][t 0..255][128 w]
__device__ float g_WB[6291456];    // [cb][bt 0..11][chunk 0..63][kp 0..1][lane][4w]
__device__ float g_dpart[65536];   // [tb 0..3][row 0..16383]

__device__ __forceinline__ float tf32r(float x) {
    float y; asm("cvt.rna.tf32.f32 %0, %1;" : "=f"(y) : "f"(x)); return y;
}
__device__ __forceinline__ uint32_t smem_u32(const void* p) {
    uint32_t a;
    asm("{ .reg .u64 t; cvta.to.shared.u64 t, %1; cvt.u32.u64 %0, t; }" : "=r"(a) : "l"(p));
    return a;
}
__device__ __forceinline__ void cp16(uint32_t dst, const void* src) {
    asm volatile("cp.async.cg.shared.global [%0], [%1], 16;" :: "r"(dst), "l"(src));
}
__device__ __forceinline__ void lds128(uint32_t* r, uint32_t a) {
    asm volatile("ld.shared.v4.b32 {%0,%1,%2,%3}, [%4];"
                 : "=r"(r[0]), "=r"(r[1]), "=r"(r[2]), "=r"(r[3]) : "r"(a));
}
__device__ __forceinline__ void mma_tf32(float* c, const uint32_t* a, const uint32_t* b) {
    asm volatile(
        "mma.sync.aligned.m16n8k8.row.col.f32.tf32.tf32.f32 "
        "{%0,%1,%2,%3}, {%4,%5,%6,%7}, {%8,%9}, {%0,%1,%2,%3};\n"
        : "+f"(c[0]), "+f"(c[1]), "+f"(c[2]), "+f"(c[3])
        : "r"(a[0]), "r"(a[1]), "r"(a[2]), "r"(a[3]), "r"(b[0]), "r"(b[1]));
}

// ---- merged preround: blocks [0,4096) do x (+decay), [4096,5632) do W ----
__global__ __launch_bounds__(256) void preround_all(
    const float* __restrict__ x, const float* __restrict__ Wd,
    const float* __restrict__ Wi, const float* __restrict__ Wa)
{
    __shared__ float sm[16 * 516];
    const int tid = threadIdx.x;
    if (blockIdx.x < 4096) {
        // ---- x path (R13 verbatim) ----
        const int rt = blockIdx.x >> 2, tb = blockIdx.x & 3;
        const float* src = x + (size_t)rt * 16 * D_MODEL + tb * 512;
        #pragma unroll
        for (int i = 0; i < 8; i++) {
            int f4 = tid + i * 256;
            int row = f4 >> 7, c4 = f4 & 127;
            float4 v = *(const float4*)(src + (size_t)row * D_MODEL + c4 * 4);
            v.x = tf32r(v.x); v.y = tf32r(v.y); v.z = tf32r(v.z); v.w = tf32r(v.w);
            *(float4*)&sm[row * 516 + c4 * 4] = v;
        }
        __syncthreads();
        char* dst = (char*)g_xA + (size_t)rt * 131072 + (size_t)tb * 64 * 512;
        #pragma unroll
        for (int i = 0; i < 8; i++) {
            int f4 = tid + i * 256;
            int tl = f4 >> 5, lane = f4 & 31;
            int g = lane >> 2, tg = lane & 3;
            float4 v;
            v.x = sm[ g      * 516 + tl * 8 + tg    ];
            v.y = sm[(g + 8) * 516 + tl * 8 + tg    ];
            v.z = sm[ g      * 516 + tl * 8 + tg + 4];
            v.w = sm[(g + 8) * 516 + tl * 8 + tg + 4];
            *(float4*)(dst + (size_t)tl * 512 + lane * 16) = v;
        }
        // conflict-free fused decay partial
        const int r = tid >> 4, sub = tid & 15;
        const float4* wd4 = (const float4*)Wd + tb * 128;
        float s = 0.f;
        #pragma unroll
        for (int j = 0; j < 8; j++) {
            int jj = (j + sub) & 7;
            float4 a = *(const float4*)&sm[r * 516 + sub * 32 + jj * 4];
            float4 w = wd4[sub * 8 + jj];
            s += a.x * w.x + a.y * w.y + a.z * w.z + a.w * w.w;
        }
        #pragma unroll
        for (int o = 1; o < 16; o <<= 1) s += __shfl_xor_sync(0xFFFFFFFFu, s, o);
        if (sub == 0) g_dpart[tb * 16384 + rt * 16 + r] = s;
    } else {
        // ---- W path: kt-paired B-fragment layout ----
        const int b  = blockIdx.x - 4096;
        const int q  = b & 3;
        const int bt = (b >> 2) % 12;
        const int cb = b / 48;
        const float* src = (bt < 8)
            ? Wi + (size_t)(cb * 64 + bt * 8) * D_MODEL
            : Wa + (size_t)(cb * 32 + (bt - 8) * 8) * D_MODEL;
        src += q * 512;
        #pragma unroll
        for (int i = 0; i < 4; i++) {
            int f4 = tid + i * 256;
            int r = f4 >> 7, c4 = f4 & 127;
            float4 v = *(const float4*)(src + (size_t)r * D_MODEL + c4 * 4);
            v.x = tf32r(v.x); v.y = tf32r(v.y); v.z = tf32r(v.z); v.w = tf32r(v.w);
            *(float4*)&sm[r * 516 + c4 * 4] = v;
        }
        __syncthreads();
        float4* dst4 = (float4*)(g_WB + (size_t)(cb * 12 + bt) * 16384);
        #pragma unroll
        for (int i = 0; i < 4; i++) {
            int f4 = tid + i * 256;               // 0..1023
            int tp = f4 >> 5, lane = f4 & 31;     // t-pair within q, lane
            int g = lane >> 2, tg = lane & 3;
            int lta = tp * 2, ltb = tp * 2 + 1;   // local t indices
            float4 v;
            v.x = sm[g * 516 + lta * 8 + tg    ]; // kt_a, j0
            v.y = sm[g * 516 + lta * 8 + tg + 4]; // kt_a, j1
            v.z = sm[g * 516 + ltb * 8 + tg    ]; // kt_b, j0
            v.w = sm[g * 516 + ltb * 8 + tg + 4]; // kt_b, j1
            // chunk = q*16 + tp>>1, kp = tp&1
            dst4[(q * 16 + (tp >> 1)) * 64 + (tp & 1) * 32 + lane] = v;
        }
    }
}

// ---- main: 128 thr, 2x2 warps, 4 stages, B via LDS.128 kt-pairs ----
__global__ void __launch_bounds__(128, 2) givens_main(
    const float* __restrict__ h_prev, const float* __restrict__ b_angle,
    const float* __restrict__ b_decay, const float* __restrict__ b_in,
    float* __restrict__ out)
{
    extern __shared__ __align__(1024) char smem[];
    const uint32_t sb = smem_u32(smem);
    const int tid = threadIdx.x, warp = tid >> 5, lane = tid & 31;
    const int g = lane >> 2, tg = lane & 3;
    const int wm = warp >> 1, wn = warp & 1;            // 2x2 warp grid
    const int by = blockIdx.y, cb = blockIdx.x;
    const int m0 = by * MT, n0 = cb * NT, a0 = n0 >> 1;

    const char* xA = (const char*)g_xA;
    const char* WB = (const char*)g_WB;
    const size_t axbase = (size_t)by * 1048576 + (size_t)warp * 512 + lane * 16;
    const size_t wbbase = (size_t)cb * 786432 + (size_t)(tid >> 6) * 65536
                        + ((tid >> 4) & 3) * 256 + (tid & 15) * 16;

    float ci[4][4][4] = {};   // mi, nb, frag
    float ca[4][2][4] = {};   // mi, na, frag

    #define ISSUE(CHUNK) do {                                                   \
        uint32_t sd = sb + ((CHUNK) & 3) * STAGE_BYTES;                          \
        const char* xs = xA + axbase + (size_t)(CHUNK) * 2048;                   \
        const char* ws = WB + wbbase + (size_t)(CHUNK) * 1024;                   \
        _Pragma("unroll")                                                        \
        for (int it = 0; it < 8; it++)                                           \
            cp16(sd + tid * 16 + it * 2048, xs + (size_t)it * 131072);           \
        _Pragma("unroll")                                                        \
        for (int ib = 0; ib < 6; ib++)                                           \
            cp16(sd + 16384 + ib * 2048 + tid * 16, ws + (size_t)ib * 131072);   \
        asm volatile("cp.async.commit_group;" ::: "memory");                     \
    } while (0)

    #define COMPUTE(CHUNK) do {                                                  \
        const uint32_t sa = sb + ((CHUNK) & 3) * STAGE_BYTES;                     \
        _Pragma("unroll")                                                         \
        for (int kp = 0; kp < 2; kp++) {                                          \
            uint32_t a0_[4][4], a1_[4][4];                                        \
            _Pragma("unroll")                                                     \
            for (int mi = 0; mi < 4; mi++)                                        \
                lds128(a0_[mi], sa + (uint32_t)(((wm * 4 + mi) * 4 + kp * 2    ) * 512) + lane * 16); \
            _Pragma("unroll")                                                     \
            for (int mi = 0; mi < 4; mi++)                                        \
                lds128(a1_[mi], sa + (uint32_t)(((wm * 4 + mi) * 4 + kp * 2 + 1) * 512) + lane * 16); \
            _Pragma("unroll")                                                     \
            for (int nb = 0; nb < 4; nb++) {                                      \
                uint32_t bp[4];                                                   \
                lds128(bp, sa + A_STAGE + (uint32_t)((wn * 4 + nb) * 1024 + kp * 512) + lane * 16); \
                _Pragma("unroll")                                                 \
                for (int mi = 0; mi < 4; mi++) {                                  \
                    mma_tf32(ci[mi][nb], a0_[mi], bp);                            \
                    mma_tf32(ci[mi][nb], a1_[mi], bp + 2);                        \
                }                                                                 \
            }                                                                     \
            _Pragma("unroll")                                                     \
            for (int na = 0; na < 2; na++) {                                      \
                uint32_t bp[4];                                                   \
                lds128(bp, sa + A_STAGE + (uint32_t)((8 + wn * 2 + na) * 1024 + kp * 512) + lane * 16); \
                _Pragma("unroll")                                                 \
                for (int mi = 0; mi < 4; mi++) {                                  \
                    mma_tf32(ca[mi][na], a0_[mi], bp);                            \
                    mma_tf32(ca[mi][na], a1_[mi], bp + 2);                        \
                }                                                                 \
            }                                                                     \
        }                                                                         \
    } while (0)

    ISSUE(0);
    ISSUE(1);

    #pragma unroll 1
    for (int cc = 0; cc < 32; cc++) {
        const int c0 = cc * 2;
        asm volatile("cp.async.wait_group 0;" ::: "memory");
        __syncthreads();
        if (c0 + 2 < 64) ISSUE(c0 + 2);
        if (c0 + 3 < 64) ISSUE(c0 + 3);
        COMPUTE(c0);
        COMPUTE(c0 + 1);
    }
    __syncthreads();

    // ---- epilogue ----
    float* ang_sm = (float*)smem;                       // 128 x 33 (stage0 reuse)
    #pragma unroll
    for (int mi = 0; mi < 4; mi++)
    #pragma unroll
    for (int na = 0; na < 2; na++) {
        int rm  = wm * 64 + mi * 16 + g;
        int cbp = wn * 16 + na * 8 + 2 * tg;
        float bA0 = b_angle[a0 + cbp], bA1 = b_angle[a0 + cbp + 1];
        ang_sm[ rm      * 33 + cbp    ] = ca[mi][na][0] + bA0;
        ang_sm[ rm      * 33 + cbp + 1] = ca[mi][na][1] + bA1;
        ang_sm[(rm + 8) * 33 + cbp    ] = ca[mi][na][2] + bA0;
        ang_sm[(rm + 8) * 33 + cbp + 1] = ca[mi][na][3] + bA1;
    }
    const float bdec = b_decay[0];
    float drow[4][2];
    #pragma unroll
    for (int mi = 0; mi < 4; mi++)
    #pragma unroll
    for (int h = 0; h < 2; h++) {
        int r = m0 + wm * 64 + mi * 16 + g + h * 8;
        float s = g_dpart[r] + g_dpart[16384 + r] + g_dpart[32768 + r] + g_dpart[49152 + r];
        drow[mi][h] = 1.f / (1.f + __expf(-(s + bdec)));
    }
    __syncthreads();

    #pragma unroll
    for (int mi = 0; mi < 4; mi++)
    #pragma unroll
    for (int nb = 0; nb < 4; nb++) {
        int cloc = wn * 32 + nb * 8 + 2 * tg;
        float2 bi2 = *(const float2*)&b_in[n0 + cloc];
        #pragma unroll
        for (int h = 0; h < 2; h++) {
            int rloc = wm * 64 + mi * 16 + g + h * 8;
            size_t goff = (size_t)(m0 + rloc) * D_MODEL + n0 + cloc;
            float theta = ang_sm[rloc * 33 + (cloc >> 1)];
            float sn, cs;
            __sincosf(theta, &sn, &cs);
            float2 hp = *(const float2*)&h_prev[goff];
            float d = drow[mi][h];
            float2 o;
            o.x = d * (cs * hp.x - sn * hp.y) + ci[mi][nb][h * 2 + 0] + bi2.x;
            o.y = d * (sn * hp.x + cs * hp.y) + ci[mi][nb][h * 2 + 1] + bi2.y;
            *(float2*)&out[goff] = o;
        }
    }
    #undef ISSUE
    #undef COMPUTE
}

extern "C" void kernel_launch(void* const* d_in, const int* in_sizes, int n_in,
                              void* d_out, int out_size) {
    const float* x       = (const float*)d_in[0];
    const float* h_prev  = (const float*)d_in[1];
    const float* W_angle = (const float*)d_in[2];
    const float* b_angle = (const float*)d_in[3];
    const float* W_decay = (const float*)d_in[4];
    const float* b_decay = (const float*)d_in[5];
    const float* W_in    = (const float*)d_in[6];
    const float* b_in    = (const float*)d_in[7];

    preround_all<<<5632, 256>>>(x, W_decay, W_in, W_angle);

    cudaFuncSetAttribute(givens_main, cudaFuncAttributeMaxDynamicSharedMemorySize, SMEM_TOTAL);
    dim3 grid(D_MODEL / NT, BATCH / MT);
    givens_main<<<grid, 128, SMEM_TOTAL>>>(h_prev, b_angle, b_decay, b_in, (float*)d_out);
}

// round 16
// speedup vs baseline: 2.1040x; 1.7135x over previous
#include <cuda_runtime.h>
#include <cuda_fp16.h>
#include <cstdint>

#define D_MODEL 2048
#define BATCH   16384
#define MT 128
#define NT 64
#define A_ST 8192
#define STAGE_BYTES 14336        // A 8KB + B 6KB
#define STAGES 8
#define SMEM_TOTAL (STAGES*STAGE_BYTES + 512)   // 115200/CTA, 2 CTA/SM

// scratch: x (fp16, A-fragment order), W (fp16, B-fragment order), decay partials
__device__ __half g_xA[33554432];  // [rt 0..1023][kstep 0..127][lane][8 halves] (64MB)
__device__ __half g_WB[6291456];   // [cb][bt 0..11][chunk 0..63][lane][8 halves] (12MB)
__device__ float  g_dpart[65536];  // [tb 0..3][row 0..16383]

__device__ __forceinline__ uint32_t pack2(float a, float b) {
    __half2 h = __floats2half2_rn(a, b);     // a -> low, b -> high
    return *(uint32_t*)&h;
}
__device__ __forceinline__ uint32_t smem_u32(const void* p) {
    uint32_t a;
    asm("{ .reg .u64 t; cvta.to.shared.u64 t, %1; cvt.u32.u64 %0, t; }" : "=r"(a) : "l"(p));
    return a;
}
__device__ __forceinline__ void cp16(uint32_t dst, const void* src) {
    asm volatile("cp.async.cg.shared.global [%0], [%1], 16;" :: "r"(dst), "l"(src));
}
__device__ __forceinline__ void lds128(uint32_t* r, uint32_t a) {
    asm volatile("ld.shared.v4.b32 {%0,%1,%2,%3}, [%4];"
                 : "=r"(r[0]), "=r"(r[1]), "=r"(r[2]), "=r"(r[3]) : "r"(a));
}
__device__ __forceinline__ void mma_f16(float* c, const uint32_t* a, const uint32_t* b) {
    asm volatile(
        "mma.sync.aligned.m16n8k16.row.col.f32.f16.f16.f32 "
        "{%0,%1,%2,%3}, {%4,%5,%6,%7}, {%8,%9}, {%0,%1,%2,%3};\n"
        : "+f"(c[0]), "+f"(c[1]), "+f"(c[2]), "+f"(c[3])
        : "r"(a[0]), "r"(a[1]), "r"(a[2]), "r"(a[3]), "r"(b[0]), "r"(b[1]));
}

// ---- merged preround: blocks [0,4096) x (+decay), [4096,5632) W ----
__global__ __launch_bounds__(256) void preround_all(
    const float* __restrict__ x, const float* __restrict__ Wd,
    const float* __restrict__ Wi, const float* __restrict__ Wa)
{
    __shared__ float sm[16 * 516];
    const int tid = threadIdx.x;
    if (blockIdx.x < 4096) {
        const int rt = blockIdx.x >> 2, tb = blockIdx.x & 3;
        const float* src = x + (size_t)rt * 16 * D_MODEL + tb * 512;
        #pragma unroll
        for (int i = 0; i < 8; i++) {
            int f4 = tid + i * 256;
            int row = f4 >> 7, c4 = f4 & 127;
            *(float4*)&sm[row * 516 + c4 * 4] =
                *(const float4*)(src + (size_t)row * D_MODEL + c4 * 4);
        }
        __syncthreads();
        // fp16 A-fragment pack: granule f -> (kstep_local, lane)
        char* dst = (char*)g_xA + (size_t)rt * 65536 + (size_t)tb * 32 * 512;
        #pragma unroll
        for (int i = 0; i < 4; i++) {
            int f = tid + i * 256;                // 0..1023
            int ks = f >> 5, lane = f & 31;
            int g = lane >> 2, tg = lane & 3;
            int kb = ks * 16 + 2 * tg;
            uint4 v;
            v.x = pack2(sm[ g      * 516 + kb    ], sm[ g      * 516 + kb + 1]);
            v.y = pack2(sm[(g + 8) * 516 + kb    ], sm[(g + 8) * 516 + kb + 1]);
            v.z = pack2(sm[ g      * 516 + kb + 8], sm[ g      * 516 + kb + 9]);
            v.w = pack2(sm[(g + 8) * 516 + kb + 8], sm[(g + 8) * 516 + kb + 9]);
            *(uint4*)(dst + (size_t)ks * 512 + lane * 16) = v;
        }
        // fused decay partial (fp32 x, conflict-free rotation)
        const int r = tid >> 4, sub = tid & 15;
        const float4* wd4 = (const float4*)Wd + tb * 128;
        float s = 0.f;
        #pragma unroll
        for (int j = 0; j < 8; j++) {
            int jj = (j + sub) & 7;
            float4 a = *(const float4*)&sm[r * 516 + sub * 32 + jj * 4];
            float4 w = wd4[sub * 8 + jj];
            s += a.x * w.x + a.y * w.y + a.z * w.z + a.w * w.w;
        }
        #pragma unroll
        for (int o = 1; o < 16; o <<= 1) s += __shfl_xor_sync(0xFFFFFFFFu, s, o);
        if (sub == 0) g_dpart[tb * 16384 + rt * 16 + r] = s;
    } else {
        const int b  = blockIdx.x - 4096;
        const int q  = b & 3;
        const int bt = (b >> 2) % 12;
        const int cb = b / 48;
        const float* src = (bt < 8)
            ? Wi + (size_t)(cb * 64 + bt * 8) * D_MODEL
            : Wa + (size_t)(cb * 32 + (bt - 8) * 8) * D_MODEL;
        src += q * 512;
        #pragma unroll
        for (int i = 0; i < 4; i++) {
            int f4 = tid + i * 256;
            int r = f4 >> 7, c4 = f4 & 127;
            *(float4*)&sm[r * 516 + c4 * 4] =
                *(const float4*)(src + (size_t)r * D_MODEL + c4 * 4);
        }
        __syncthreads();
        // fp16 B-fragment pack: per chunk per lane 16B = both ksteps
        char* dst = (char*)g_WB + (size_t)(cb * 12 + bt) * 32768;
        #pragma unroll
        for (int i = 0; i < 2; i++) {
            int f = tid + i * 256;                // 0..511
            int cl = f >> 5, lane = f & 31;       // chunk_local 0..15
            int g = lane >> 2, tg = lane & 3;
            int kb = cl * 32 + 2 * tg;
            uint4 v;
            v.x = pack2(sm[g * 516 + kb     ], sm[g * 516 + kb +  1]);  // kstep0 b0
            v.y = pack2(sm[g * 516 + kb +  8], sm[g * 516 + kb +  9]);  // kstep0 b1
            v.z = pack2(sm[g * 516 + kb + 16], sm[g * 516 + kb + 17]);  // kstep1 b0
            v.w = pack2(sm[g * 516 + kb + 24], sm[g * 516 + kb + 25]);  // kstep1 b1
            *(uint4*)(dst + (size_t)(q * 16 + cl) * 512 + lane * 16) = v;
        }
    }
}

// ---- main: fp16 MMA, 128 thr, 2x2 warps, 8 stages, one sync per 4 chunks ----
__global__ void __launch_bounds__(128, 2) givens_main(
    const float* __restrict__ h_prev, const float* __restrict__ b_angle,
    const float* __restrict__ b_decay, const float* __restrict__ b_in,
    float* __restrict__ out)
{
    extern __shared__ __align__(1024) char smem[];
    const uint32_t sb = smem_u32(smem);
    const int tid = threadIdx.x, warp = tid >> 5, lane = tid & 31;
    const int g = lane >> 2, tg = lane & 3;
    const int wm = warp >> 1, wn = warp & 1;            // 2x2 warp grid
    const int by = blockIdx.y, cb = blockIdx.x;
    const int m0 = by * MT, n0 = cb * NT, a0 = n0 >> 1;

    // A: 512 granules/chunk -> 4/thread; B: 384 -> 3/thread
    const char* xAc = (const char*)g_xA + (size_t)by * 524288;
    const char* WBc = (const char*)g_WB + (size_t)cb * 393216;
    const char* asrc[4]; uint32_t adst[4];
    #pragma unroll
    for (int it = 0; it < 4; it++) {
        int f = it * 128 + tid;
        int rg = f >> 6, s = (f >> 5) & 1, ln = f & 31;
        asrc[it] = xAc + (size_t)rg * 65536 + s * 512 + ln * 16;
        adst[it] = (uint32_t)(f * 16);
    }
    const char* bsrc[3]; uint32_t bdst[3];
    #pragma unroll
    for (int ib = 0; ib < 3; ib++) {
        int f = ib * 128 + tid;
        int bt = f >> 5, ln = f & 31;
        bsrc[ib] = WBc + (size_t)bt * 32768 + ln * 16;
        bdst[ib] = (uint32_t)(A_ST + f * 16);
    }

    float ci[4][4][4] = {};   // mi, nb, frag
    float ca[4][2][4] = {};   // mi, na, frag

    #define ISSUE(CHUNK) do {                                                   \
        uint32_t sd = sb + ((CHUNK) & 7) * STAGE_BYTES;                          \
        _Pragma("unroll")                                                        \
        for (int it = 0; it < 4; it++)                                           \
            cp16(sd + adst[it], asrc[it] + (size_t)(CHUNK) * 1024);              \
        _Pragma("unroll")                                                        \
        for (int ib = 0; ib < 3; ib++)                                           \
            cp16(sd + bdst[ib], bsrc[ib] + (size_t)(CHUNK) * 512);               \
        asm volatile("cp.async.commit_group;" ::: "memory");                     \
    } while (0)

    #define COMPUTE(CHUNK) do {                                                  \
        const uint32_t sa = sb + ((CHUNK) & 7) * STAGE_BYTES;                     \
        uint32_t bfr[6][4];                                                       \
        _Pragma("unroll")                                                         \
        for (int j = 0; j < 4; j++)                                               \
            lds128(bfr[j], sa + A_ST + (uint32_t)((wn * 4 + j) * 512) + lane * 16); \
        _Pragma("unroll")                                                         \
        for (int j = 0; j < 2; j++)                                               \
            lds128(bfr[4 + j], sa + A_ST + (uint32_t)((8 + wn * 2 + j) * 512) + lane * 16); \
        _Pragma("unroll")                                                         \
        for (int s = 0; s < 2; s++) {                                             \
            uint32_t a[4][4];                                                     \
            _Pragma("unroll")                                                     \
            for (int mi = 0; mi < 4; mi++)                                        \
                lds128(a[mi], sa + (uint32_t)((wm * 4 + mi) * 1024 + s * 512) + lane * 16); \
            _Pragma("unroll")                                                     \
            for (int nb = 0; nb < 4; nb++)                                        \
                _Pragma("unroll")                                                 \
                for (int mi = 0; mi < 4; mi++)                                    \
                    mma_f16(ci[mi][nb], a[mi], bfr[nb] + 2 * s);                  \
            _Pragma("unroll")                                                     \
            for (int na = 0; na < 2; na++)                                        \
                _Pragma("unroll")                                                 \
                for (int mi = 0; mi < 4; mi++)                                    \
                    mma_f16(ca[mi][na], a[mi], bfr[4 + na] + 2 * s);              \
        }                                                                         \
    } while (0)

    ISSUE(0); ISSUE(1); ISSUE(2); ISSUE(3);

    #pragma unroll 1
    for (int cc = 0; cc < 16; cc++) {
        const int c0 = cc * 4;
        asm volatile("cp.async.wait_group 0;" ::: "memory");
        __syncthreads();
        if (c0 + 4 < 64) ISSUE(c0 + 4);
        if (c0 + 5 < 64) ISSUE(c0 + 5);
        if (c0 + 6 < 64) ISSUE(c0 + 6);
        if (c0 + 7 < 64) ISSUE(c0 + 7);
        COMPUTE(c0);
        COMPUTE(c0 + 1);
        COMPUTE(c0 + 2);
        COMPUTE(c0 + 3);
    }
    __syncthreads();

    // ---- epilogue (identical C-fragment mapping) ----
    float* ang_sm = (float*)smem;                       // 128 x 33 (stage reuse)
    #pragma unroll
    for (int mi = 0; mi < 4; mi++)
    #pragma unroll
    for (int na = 0; na < 2; na++) {
        int rm  = wm * 64 + mi * 16 + g;
        int cbp = wn * 16 + na * 8 + 2 * tg;
        float bA0 = b_angle[a0 + cbp], bA1 = b_angle[a0 + cbp + 1];
        ang_sm[ rm      * 33 + cbp    ] = ca[mi][na][0] + bA0;
        ang_sm[ rm      * 33 + cbp + 1] = ca[mi][na][1] + bA1;
        ang_sm[(rm + 8) * 33 + cbp    ] = ca[mi][na][2] + bA0;
        ang_sm[(rm + 8) * 33 + cbp + 1] = ca[mi][na][3] + bA1;
    }
    const float bdec = b_decay[0];
    float drow[4][2];
    #pragma unroll
    for (int mi = 0; mi < 4; mi++)
    #pragma unroll
    for (int h = 0; h < 2; h++) {
        int r = m0 + wm * 64 + mi * 16 + g + h * 8;
        float s = g_dpart[r] + g_dpart[16384 + r] + g_dpart[32768 + r] + g_dpart[49152 + r];
        drow[mi][h] = 1.f / (1.f + __expf(-(s + bdec)));
    }
    __syncthreads();

    #pragma unroll
    for (int mi = 0; mi < 4; mi++)
    #pragma unroll
    for (int nb = 0; nb < 4; nb++) {
        int cloc = wn * 32 + nb * 8 + 2 * tg;
        float2 bi2 = *(const float2*)&b_in[n0 + cloc];
        #pragma unroll
        for (int h = 0; h < 2; h++) {
            int rloc = wm * 64 + mi * 16 + g + h * 8;
            size_t goff = (size_t)(m0 + rloc) * D_MODEL + n0 + cloc;
            float theta = ang_sm[rloc * 33 + (cloc >> 1)];
            float sn, cs;
            __sincosf(theta, &sn, &cs);
            float2 hp = *(const float2*)&h_prev[goff];
            float d = drow[mi][h];
            float2 o;
            o.x = d * (cs * hp.x - sn * hp.y) + ci[mi][nb][h * 2 + 0] + bi2.x;
            o.y = d * (sn * hp.x + cs * hp.y) + ci[mi][nb][h * 2 + 1] + bi2.y;
            *(float2*)&out[goff] = o;
        }
    }
    #undef ISSUE
    #undef COMPUTE
}

extern "C" void kernel_launch(void* const* d_in, const int* in_sizes, int n_in,
                              void* d_out, int out_size) {
    const float* x       = (const float*)d_in[0];
    const float* h_prev  = (const float*)d_in[1];
    const float* W_angle = (const float*)d_in[2];
    const float* b_angle = (const float*)d_in[3];
    const float* W_decay = (const float*)d_in[4];
    const float* b_decay = (const float*)d_in[5];
    const float* W_in    = (const float*)d_in[6];
    const float* b_in    = (const float*)d_in[7];

    preround_all<<<5632, 256>>>(x, W_decay, W_in, W_angle);

    cudaFuncSetAttribute(givens_main, cudaFuncAttributeMaxDynamicSharedMemorySize, SMEM_TOTAL);
    dim3 grid(D_MODEL / NT, BATCH / MT);
    givens_main<<<grid, 128, SMEM_TOTAL>>>(h_prev, b_angle, b_decay, b_in, (float*)d_out);
}

// round 17
// speedup vs baseline: 2.2539x; 1.0712x over previous
#include <cuda_runtime.h>
#include <cuda_fp16.h>
#include <cstdint>

#define D_MODEL 2048
#define BATCH   16384
#define MT 128
#define NT 64
#define A_ST 8192
#define STAGE_BYTES 14336        // A 8KB + B 6KB
#define STAGES 5
#define SMEM_TOTAL (STAGES*STAGE_BYTES + 512)   // 72192/CTA, 3 CTA/SM = 216576

// scratch: x (fp16, A-fragment order), W (fp16, B-fragment order), decay partials
__device__ __half g_xA[33554432];  // [rt 0..1023][kstep 0..127][lane][8 halves]
__device__ __half g_WB[6291456];   // [cb][bt 0..11][chunk 0..63][lane][8 halves]
__device__ float  g_dpart[65536];  // [tb 0..3][row 0..16383]

__device__ __forceinline__ uint32_t pack2(float a, float b) {
    __half2 h = __floats2half2_rn(a, b);
    return *(uint32_t*)&h;
}
__device__ __forceinline__ uint32_t smem_u32(const void* p) {
    uint32_t a;
    asm("{ .reg .u64 t; cvta.to.shared.u64 t, %1; cvt.u32.u64 %0, t; }" : "=r"(a) : "l"(p));
    return a;
}
__device__ __forceinline__ void cp16(uint32_t dst, const void* src) {
    asm volatile("cp.async.cg.shared.global [%0], [%1], 16;" :: "r"(dst), "l"(src));
}
__device__ __forceinline__ void lds128(uint32_t* r, uint32_t a) {
    asm volatile("ld.shared.v4.b32 {%0,%1,%2,%3}, [%4];"
                 : "=r"(r[0]), "=r"(r[1]), "=r"(r[2]), "=r"(r[3]) : "r"(a));
}
__device__ __forceinline__ void mma_f16(float* c, const uint32_t* a, const uint32_t* b) {
    asm volatile(
        "mma.sync.aligned.m16n8k16.row.col.f32.f16.f16.f32 "
        "{%0,%1,%2,%3}, {%4,%5,%6,%7}, {%8,%9}, {%0,%1,%2,%3};\n"
        : "+f"(c[0]), "+f"(c[1]), "+f"(c[2]), "+f"(c[3])
        : "r"(a[0]), "r"(a[1]), "r"(a[2]), "r"(a[3]), "r"(b[0]), "r"(b[1]));
}

// ---- merged preround: blocks [0,4096) x (+decay), [4096,5632) W ----
__global__ __launch_bounds__(256) void preround_all(
    const float* __restrict__ x, const float* __restrict__ Wd,
    const float* __restrict__ Wi, const float* __restrict__ Wa)
{
    __shared__ float sm[16 * 516];
    const int tid = threadIdx.x;
    if (blockIdx.x < 4096) {
        const int rt = blockIdx.x >> 2, tb = blockIdx.x & 3;
        const float* src = x + (size_t)rt * 16 * D_MODEL + tb * 512;
        #pragma unroll
        for (int i = 0; i < 8; i++) {
            int f4 = tid + i * 256;
            int row = f4 >> 7, c4 = f4 & 127;
            *(float4*)&sm[row * 516 + c4 * 4] =
                *(const float4*)(src + (size_t)row * D_MODEL + c4 * 4);
        }
        __syncthreads();
        char* dst = (char*)g_xA + (size_t)rt * 65536 + (size_t)tb * 32 * 512;
        #pragma unroll
        for (int i = 0; i < 4; i++) {
            int f = tid + i * 256;
            int ks = f >> 5, lane = f & 31;
            int g = lane >> 2, tg = lane & 3;
            int kb = ks * 16 + 2 * tg;
            uint4 v;
            v.x = pack2(sm[ g      * 516 + kb    ], sm[ g      * 516 + kb + 1]);
            v.y = pack2(sm[(g + 8) * 516 + kb    ], sm[(g + 8) * 516 + kb + 1]);
            v.z = pack2(sm[ g      * 516 + kb + 8], sm[ g      * 516 + kb + 9]);
            v.w = pack2(sm[(g + 8) * 516 + kb + 8], sm[(g + 8) * 516 + kb + 9]);
            *(uint4*)(dst + (size_t)ks * 512 + lane * 16) = v;
        }
        const int r = tid >> 4, sub = tid & 15;
        const float4* wd4 = (const float4*)Wd + tb * 128;
        float s = 0.f;
        #pragma unroll
        for (int j = 0; j < 8; j++) {
            int jj = (j + sub) & 7;
            float4 a = *(const float4*)&sm[r * 516 + sub * 32 + jj * 4];
            float4 w = wd4[sub * 8 + jj];
            s += a.x * w.x + a.y * w.y + a.z * w.z + a.w * w.w;
        }
        #pragma unroll
        for (int o = 1; o < 16; o <<= 1) s += __shfl_xor_sync(0xFFFFFFFFu, s, o);
        if (sub == 0) g_dpart[tb * 16384 + rt * 16 + r] = s;
    } else {
        const int b  = blockIdx.x - 4096;
        const int q  = b & 3;
        const int bt = (b >> 2) % 12;
        const int cb = b / 48;
        const float* src = (bt < 8)
            ? Wi + (size_t)(cb * 64 + bt * 8) * D_MODEL
            : Wa + (size_t)(cb * 32 + (bt - 8) * 8) * D_MODEL;
        src += q * 512;
        #pragma unroll
        for (int i = 0; i < 4; i++) {
            int f4 = tid + i * 256;
            int r = f4 >> 7, c4 = f4 & 127;
            *(float4*)&sm[r * 516 + c4 * 4] =
                *(const float4*)(src + (size_t)r * D_MODEL + c4 * 4);
        }
        __syncthreads();
        char* dst = (char*)g_WB + (size_t)(cb * 12 + bt) * 32768;
        #pragma unroll
        for (int i = 0; i < 2; i++) {
            int f = tid + i * 256;
            int cl = f >> 5, lane = f & 31;
            int g = lane >> 2, tg = lane & 3;
            int kb = cl * 32 + 2 * tg;
            uint4 v;
            v.x = pack2(sm[g * 516 + kb     ], sm[g * 516 + kb +  1]);
            v.y = pack2(sm[g * 516 + kb +  8], sm[g * 516 + kb +  9]);
            v.z = pack2(sm[g * 516 + kb + 16], sm[g * 516 + kb + 17]);
            v.w = pack2(sm[g * 516 + kb + 24], sm[g * 516 + kb + 25]);
            *(uint4*)(dst + (size_t)(q * 16 + cl) * 512 + lane * 16) = v;
        }
    }
}

// ---- main: fp16 MMA, 128 thr, 2x2 warps, 5 stages, 3 CTA/SM ----
__global__ void __launch_bounds__(128, 3) givens_main(
    const float* __restrict__ h_prev, const float* __restrict__ b_angle,
    const float* __restrict__ b_decay, const float* __restrict__ b_in,
    float* __restrict__ out)
{
    extern __shared__ __align__(1024) char smem[];
    const uint32_t sb = smem_u32(smem);
    const int tid = threadIdx.x, warp = tid >> 5, lane = tid & 31;
    const int g = lane >> 2, tg = lane & 3;
    const int wm = warp >> 1, wn = warp & 1;            // 2x2 warp grid
    const int by = blockIdx.y, cb = blockIdx.x;
    const int m0 = by * MT, n0 = cb * NT, a0 = n0 >> 1;

    const char* xAc = (const char*)g_xA + (size_t)by * 524288;
    const char* WBc = (const char*)g_WB + (size_t)cb * 393216;
    const char* asrc[4]; uint32_t adst[4];
    #pragma unroll
    for (int it = 0; it < 4; it++) {
        int f = it * 128 + tid;
        int rg = f >> 6, s = (f >> 5) & 1, ln = f & 31;
        asrc[it] = xAc + (size_t)rg * 65536 + s * 512 + ln * 16;
        adst[it] = (uint32_t)(f * 16);
    }
    const char* bsrc[3]; uint32_t bdst[3];
    #pragma unroll
    for (int ib = 0; ib < 3; ib++) {
        int f = ib * 128 + tid;
        int bt = f >> 5, ln = f & 31;
        bsrc[ib] = WBc + (size_t)bt * 32768 + ln * 16;
        bdst[ib] = (uint32_t)(A_ST + f * 16);
    }

    float ci[4][4][4] = {};   // mi, nb, frag
    float ca[4][2][4] = {};   // mi, na, frag

    #define ISSUE(CHUNK) do {                                                   \
        uint32_t sd = sb + ((CHUNK) % STAGES) * STAGE_BYTES;                     \
        _Pragma("unroll")                                                        \
        for (int it = 0; it < 4; it++)                                           \
            cp16(sd + adst[it], asrc[it] + (size_t)(CHUNK) * 1024);              \
        _Pragma("unroll")                                                        \
        for (int ib = 0; ib < 3; ib++)                                           \
            cp16(sd + bdst[ib], bsrc[ib] + (size_t)(CHUNK) * 512);               \
        asm volatile("cp.async.commit_group;" ::: "memory");                     \
    } while (0)

    #define COMPUTE(CHUNK) do {                                                  \
        const uint32_t sa = sb + ((CHUNK) % STAGES) * STAGE_BYTES;                \
        uint32_t bfr[6][4];                                                       \
        _Pragma("unroll")                                                         \
        for (int j = 0; j < 4; j++)                                               \
            lds128(bfr[j], sa + A_ST + (uint32_t)((wn * 4 + j) * 512) + lane * 16); \
        _Pragma("unroll")                                                         \
        for (int j = 0; j < 2; j++)                                               \
            lds128(bfr[4 + j], sa + A_ST + (uint32_t)((8 + wn * 2 + j) * 512) + lane * 16); \
        _Pragma("unroll")                                                         \
        for (int s = 0; s < 2; s++) {                                             \
            uint32_t a[4][4];                                                     \
            _Pragma("unroll")                                                     \
            for (int mi = 0; mi < 4; mi++)                                        \
                lds128(a[mi], sa + (uint32_t)((wm * 4 + mi) * 1024 + s * 512) + lane * 16); \
            _Pragma("unroll")                                                     \
            for (int nb = 0; nb < 4; nb++)                                        \
                _Pragma("unroll")                                                 \
                for (int mi = 0; mi < 4; mi++)                                    \
                    mma_f16(ci[mi][nb], a[mi], bfr[nb] + 2 * s);                  \
            _Pragma("unroll")                                                     \
            for (int na = 0; na < 2; na++)                                        \
                _Pragma("unroll")                                                 \
                for (int mi = 0; mi < 4; mi++)                                    \
                    mma_f16(ca[mi][na], a[mi], bfr[4 + na] + 2 * s);              \
        }                                                                         \
    } while (0)

    ISSUE(0); ISSUE(1); ISSUE(2);

    #pragma unroll 1
    for (int cc = 0; cc < 32; cc++) {
        const int c0 = cc * 2;
        asm volatile("cp.async.wait_group 1;" ::: "memory");   // c0..c0+1 landed
        __syncthreads();
        if (c0 + 3 < 64) ISSUE(c0 + 3);
        else             asm volatile("cp.async.commit_group;" ::: "memory");
        if (c0 + 4 < 64) ISSUE(c0 + 4);
        else             asm volatile("cp.async.commit_group;" ::: "memory");
        COMPUTE(c0);
        COMPUTE(c0 + 1);
    }
    __syncthreads();

    // ---- epilogue ----
    float* ang_sm = (float*)smem;                       // 128 x 33 (stage reuse)
    #pragma unroll
    for (int mi = 0; mi < 4; mi++)
    #pragma unroll
    for (int na = 0; na < 2; na++) {
        int rm  = wm * 64 + mi * 16 + g;
        int cbp = wn * 16 + na * 8 + 2 * tg;
        float bA0 = b_angle[a0 + cbp], bA1 = b_angle[a0 + cbp + 1];
        ang_sm[ rm      * 33 + cbp    ] = ca[mi][na][0] + bA0;
        ang_sm[ rm      * 33 + cbp + 1] = ca[mi][na][1] + bA1;
        ang_sm[(rm + 8) * 33 + cbp    ] = ca[mi][na][2] + bA0;
        ang_sm[(rm + 8) * 33 + cbp + 1] = ca[mi][na][3] + bA1;
    }
    const float bdec = b_decay[0];
    float drow[4][2];
    #pragma unroll
    for (int mi = 0; mi < 4; mi++)
    #pragma unroll
    for (int h = 0; h < 2; h++) {
        int r = m0 + wm * 64 + mi * 16 + g + h * 8;
        float s = g_dpart[r] + g_dpart[16384 + r] + g_dpart[32768 + r] + g_dpart[49152 + r];
        drow[mi][h] = 1.f / (1.f + __expf(-(s + bdec)));
    }
    __syncthreads();

    #pragma unroll
    for (int mi = 0; mi < 4; mi++)
    #pragma unroll
    for (int nb = 0; nb < 4; nb++) {
        int cloc = wn * 32 + nb * 8 + 2 * tg;
        float2 bi2 = *(const float2*)&b_in[n0 + cloc];
        #pragma unroll
        for (int h = 0; h < 2; h++) {
            int rloc = wm * 64 + mi * 16 + g + h * 8;
            size_t goff = (size_t)(m0 + rloc) * D_MODEL + n0 + cloc;
            float theta = ang_sm[rloc * 33 + (cloc >> 1)];
            float sn, cs;
            __sincosf(theta, &sn, &cs);
            float2 hp = *(const float2*)&h_prev[goff];
            float d = drow[mi][h];
            float2 o;
            o.x = d * (cs * hp.x - sn * hp.y) + ci[mi][nb][h * 2 + 0] + bi2.x;
            o.y = d * (sn * hp.x + cs * hp.y) + ci[mi][nb][h * 2 + 1] + bi2.y;
            *(float2*)&out[goff] = o;
        }
    }
    #undef ISSUE
    #undef COMPUTE
}

extern "C" void kernel_launch(void* const* d_in, const int* in_sizes, int n_in,
                              void* d_out, int out_size) {
    const float* x       = (const float*)d_in[0];
    const float* h_prev  = (const float*)d_in[1];
    const float* W_angle = (const float*)d_in[2];
    const float* b_angle = (const float*)d_in[3];
    const float* W_decay = (const float*)d_in[4];
    const float* b_decay = (const float*)d_in[5];
    const float* W_in    = (const float*)d_in[6];
    const float* b_in    = (const float*)d_in[7];

    preround_all<<<5632, 256>>>(x, W_decay, W_in, W_angle);

    cudaFuncSetAttribute(givens_main, cudaFuncAttributeMaxDynamicSharedMemorySize, SMEM_TOTAL);
    dim3 grid(D_MODEL / NT, BATCH / MT);
    givens_main<<<grid, 128, SMEM_TOTAL>>>(h_prev, b_angle, b_decay, b_in, (float*)d_out);
}